// round 17
// baseline (speedup 1.0000x reference)
#include <cuda_runtime.h>
#include <cuda_fp16.h>
#include <cstdint>
#include <math.h>

#define NB    8
#define NPix  1024
#define C_IN  384
#define C_QKV 1536
#define C_MG  384
#define C_F1  768
#define C_F2  384
#define DK    32
#define DV    128
#define NPARTS 64

__device__ __half g_qh[NB * 8 * 32 * NPix];
__device__ __half g_kh[NB * 8 * 32 * NPix];
__device__ __half g_vh[NB * 8 * 128 * NPix];
__device__ __half g_obuf[NB * 1024 * NPix];
__device__ float  g_y2 [NB * C_MG * NPix];
__device__ float  g_xr [NB * C_IN * NPix];
__device__ __half g_xrh[NB * C_IN * NPix];
__device__ __half g_xh [NB * C_IN * NPix];
__device__ float  g_h1 [NB * C_F1 * NPix];
__device__ __half g_h1h[NB * C_F1 * NPix];
__device__ float  g_y3 [NB * C_F2 * NPix];
__device__ float  g_part[NPARTS * C_QKV * 2];
__device__ float  g_sc_qkv[C_QKV], g_sh_qkv[C_QKV];
__device__ float  g_sc_mg [C_MG ], g_sh_mg [C_MG ];
__device__ float  g_sc_f1 [C_F1 ], g_sh_f1 [C_F1 ];
__device__ float  g_sc_f2 [C_F2 ], g_sh_f2 [C_F2 ];
__device__ __half g_wq[C_QKV * C_IN];
__device__ __half g_wm[C_MG * 1024];
__device__ __half g_w1[C_F1 * C_IN];
__device__ __half g_w2[C_F2 * C_F1];

__device__ __forceinline__ float gelu_exact(float v) { return v * normcdff(v); }

__device__ __forceinline__ float ex2f(float x) {
    float r;
    asm("ex2.approx.f32 %0, %1;" : "=f"(r) : "f"(x));
    return r;
}

__device__ __forceinline__ void mma_f16_16x8x16(float d[4], const uint32_t a[4],
                                                uint32_t b0, uint32_t b1)
{
    asm volatile(
        "mma.sync.aligned.m16n8k16.row.col.f32.f16.f16.f32 "
        "{%0,%1,%2,%3}, {%4,%5,%6,%7}, {%8,%9}, {%0,%1,%2,%3};"
        : "+f"(d[0]), "+f"(d[1]), "+f"(d[2]), "+f"(d[3])
        : "r"(a[0]), "r"(a[1]), "r"(a[2]), "r"(a[3]), "r"(b0), "r"(b1));
}

__device__ __forceinline__ void ldm_x4(uint32_t r[4], uint32_t addr) {
    asm volatile("ldmatrix.sync.aligned.m8n8.x4.shared.b16 {%0,%1,%2,%3}, [%4];"
                 : "=r"(r[0]), "=r"(r[1]), "=r"(r[2]), "=r"(r[3]) : "r"(addr));
}
__device__ __forceinline__ void ldm_x4t(uint32_t r[4], uint32_t addr) {
    asm volatile("ldmatrix.sync.aligned.m8n8.x4.trans.shared.b16 {%0,%1,%2,%3}, [%4];"
                 : "=r"(r[0]), "=r"(r[1]), "=r"(r[2]), "=r"(r[3]) : "r"(addr));
}

__device__ __forceinline__ void cp16(uint32_t saddr, const void* gptr) {
    asm volatile("cp.async.cg.shared.global [%0], [%1], 16;" :: "r"(saddr), "l"(gptr));
}
#define CP_COMMIT asm volatile("cp.async.commit_group;" ::: "memory")
#define CP_WAIT1  asm volatile("cp.async.wait_group 1;" ::: "memory")
#define CP_WAIT0  asm volatile("cp.async.wait_group 0;" ::: "memory")

// ---------------- weights + x : fp32 -> fp16 (single launch) ----------------
// chunk counts: wq 147456, wm 98304, w1 73728, w2 73728, x 786432  (total 1179648)
__global__ void round_all(const float* __restrict__ w0, __half* __restrict__ o0,
                          const float* __restrict__ w1, __half* __restrict__ o1,
                          const float* __restrict__ w2, __half* __restrict__ o2,
                          const float* __restrict__ w3, __half* __restrict__ o3,
                          const float* __restrict__ w4, __half* __restrict__ o4)
{
    int i = blockIdx.x * 256 + threadIdx.x;
    const float* w; __half* o; int j = i;
    if (j < 147456)                 { w = w0; o = o0; }
    else if ((j -= 147456) < 98304) { w = w1; o = o1; }
    else if ((j -=  98304) < 73728) { w = w2; o = o2; }
    else if ((j -=  73728) < 73728) { w = w3; o = o3; }
    else                            { j -= 73728; w = w4; o = o4; }
    float4 v = ((const float4*)w)[j];
    __half2* d = (__half2*)o + 2 * j;
    d[0] = __floats2half2_rn(v.x, v.y);
    d[1] = __floats2half2_rn(v.z, v.w);
}

// ---------------- fp16 GEMM + fused BN partial stats -----------------------
#define F16_STG_B 18944
#define GEMM_SMEM (3 * F16_STG_B)

__global__ void __launch_bounds__(256, 2) f16_gemm(const __half* __restrict__ A,
                                                   const __half* __restrict__ Bg,
                                                   float* __restrict__ Cg,
                                                   float* __restrict__ part,
                                                   __half* __restrict__ qh,
                                                   __half* __restrict__ kh,
                                                   __half* __restrict__ vh,
                                                   int M, int N, int K)
{
    extern __shared__ char smc[];
    const uint32_t sbase = (uint32_t)__cvta_generic_to_shared(smc);
    float* sm = (float*)smc;

    const int tid  = threadIdx.x;
    const int wid  = tid >> 5;
    const int lane = tid & 31;
    const int gid  = lane >> 2;
    const int tid4 = lane & 3;
    const int wm   = (wid & 1) * 64;
    const int wn   = (wid >> 1) * 32;

    const int mBase = blockIdx.x * 128, nBase = blockIdx.y * 128;
    const __half* Bp = Bg + (size_t)blockIdx.z * K * N;
    float*        Cp = Cg + (size_t)blockIdx.z * M * N;

    const int nst = K >> 5;

    const int lt = lane >> 3, lr = lane & 7;
    uint32_t aoff[4];
#pragma unroll
    for (int mi = 0; mi < 4; ++mi)
        aoff[mi] = (uint32_t)((wm + mi * 16 + (lt & 1) * 8 + lr) * 80 + (lt >> 1) * 16);
    uint32_t boff[2];
#pragma unroll
    for (int nip = 0; nip < 2; ++nip)
        boff[nip] = (uint32_t)(10240 + ((lt & 1) * 8 + lr) * 272 +
                               (wn + nip * 16 + (lt >> 1) * 8) * 2);

#define ISSUE_STAGE(s_) do {                                                   \
        int _s = (s_);                                                         \
        uint32_t sa = sbase + (_s % 3) * F16_STG_B;                            \
        int _k0 = _s << 5;                                                     \
        _Pragma("unroll")                                                      \
        for (int t = 0; t < 2; ++t) {                                          \
            int c = tid + t * 256;                                             \
            int m = c >> 2, j = c & 3;                                         \
            cp16(sa + m * 80 + j * 16,                                         \
                 &A[(size_t)(mBase + m) * K + _k0 + (j << 3)]);                \
        }                                                                      \
        _Pragma("unroll")                                                      \
        for (int t = 0; t < 2; ++t) {                                          \
            int c = tid + t * 256;                                             \
            int k = c >> 4, j = c & 15;                                        \
            cp16(sa + 10240 + k * 272 + j * 16,                                \
                 &Bp[(size_t)(_k0 + k) * N + nBase + (j << 3)]);               \
        }                                                                      \
    } while (0)

    float d[4][4][4];
#pragma unroll
    for (int mi = 0; mi < 4; ++mi)
#pragma unroll
        for (int ni = 0; ni < 4; ++ni)
#pragma unroll
            for (int r = 0; r < 4; ++r) d[mi][ni][r] = 0.f;

    ISSUE_STAGE(0); CP_COMMIT;
    ISSUE_STAGE(1); CP_COMMIT;

    for (int s = 0; s < nst; ++s) {
        CP_WAIT1;
        __syncthreads();
        if (s + 2 < nst) ISSUE_STAGE(s + 2);
        CP_COMMIT;

        uint32_t stg = sbase + (s % 3) * F16_STG_B;

#pragma unroll
        for (int ks = 0; ks < 2; ++ks) {
            uint32_t af[4][4];
#pragma unroll
            for (int mi = 0; mi < 4; ++mi)
                ldm_x4(af[mi], stg + aoff[mi] + ks * 32);
            uint32_t bf0[4], bf1[4];
            ldm_x4t(bf0, stg + boff[0] + ks * 4352);
            ldm_x4t(bf1, stg + boff[1] + ks * 4352);
#pragma unroll
            for (int mi = 0; mi < 4; ++mi) {
                mma_f16_16x8x16(d[mi][0], af[mi], bf0[0], bf0[1]);
                mma_f16_16x8x16(d[mi][1], af[mi], bf0[2], bf0[3]);
                mma_f16_16x8x16(d[mi][2], af[mi], bf1[0], bf1[1]);
                mma_f16_16x8x16(d[mi][3], af[mi], bf1[2], bf1[3]);
            }
        }
    }
#undef ISSUE_STAGE

    float sl[4], ql[4], sh_[4], qh_[4];
#pragma unroll
    for (int mi = 0; mi < 4; ++mi) {
        sl[mi] = ql[mi] = sh_[mi] = qh_[mi] = 0.f;
        int rowl = wm + mi * 16 + gid;
        if (qh) {
            int m0 = mBase + rowl, m1 = m0 + 8;
            int h0 = m0 / 192, r0 = m0 % 192;
            int h1r = m1 / 192, r1 = m1 % 192;
            size_t bh0 = (size_t)(blockIdx.z * 8 + h0);
            size_t bh1 = (size_t)(blockIdx.z * 8 + h1r);
            __half* p0 = (r0 < 32) ? qh + (bh0 * 32 + r0) * NPix
                        : (r0 < 64) ? kh + (bh0 * 32 + r0 - 32) * NPix
                                    : vh + (bh0 * 128 + r0 - 64) * NPix;
            __half* p1 = (r1 < 32) ? qh + (bh1 * 32 + r1) * NPix
                        : (r1 < 64) ? kh + (bh1 * 32 + r1 - 32) * NPix
                                    : vh + (bh1 * 128 + r1 - 64) * NPix;
#pragma unroll
            for (int ni = 0; ni < 4; ++ni) {
                int col = nBase + wn + ni * 8 + 2 * tid4;
                sl[mi] += d[mi][ni][0] + d[mi][ni][1];
                ql[mi] += d[mi][ni][0] * d[mi][ni][0] + d[mi][ni][1] * d[mi][ni][1];
                sh_[mi] += d[mi][ni][2] + d[mi][ni][3];
                qh_[mi] += d[mi][ni][2] * d[mi][ni][2] + d[mi][ni][3] * d[mi][ni][3];
                *(__half2*)(p0 + col) = __floats2half2_rn(d[mi][ni][0], d[mi][ni][1]);
                *(__half2*)(p1 + col) = __floats2half2_rn(d[mi][ni][2], d[mi][ni][3]);
            }
        } else {
            int row = mBase + rowl;
#pragma unroll
            for (int ni = 0; ni < 4; ++ni) {
                int col = nBase + wn + ni * 8 + 2 * tid4;
                sl[mi] += d[mi][ni][0] + d[mi][ni][1];
                ql[mi] += d[mi][ni][0] * d[mi][ni][0] + d[mi][ni][1] * d[mi][ni][1];
                sh_[mi] += d[mi][ni][2] + d[mi][ni][3];
                qh_[mi] += d[mi][ni][2] * d[mi][ni][2] + d[mi][ni][3] * d[mi][ni][3];
                *(float2*)&Cp[(size_t)row * N + col] =
                    make_float2(d[mi][ni][0], d[mi][ni][1]);
                *(float2*)&Cp[(size_t)(row + 8) * N + col] =
                    make_float2(d[mi][ni][2], d[mi][ni][3]);
            }
        }
#pragma unroll
        for (int off = 1; off <= 2; off <<= 1) {
            sl[mi]  += __shfl_xor_sync(0xffffffffu, sl[mi],  off);
            ql[mi]  += __shfl_xor_sync(0xffffffffu, ql[mi],  off);
            sh_[mi] += __shfl_xor_sync(0xffffffffu, sh_[mi], off);
            qh_[mi] += __shfl_xor_sync(0xffffffffu, qh_[mi], off);
        }
    }
    __syncthreads();
    float* pb = sm;
    if (tid4 == 0) {
        int g = wid >> 1;
#pragma unroll
        for (int mi = 0; mi < 4; ++mi) {
            int lr2 = wm + mi * 16 + gid;
            pb[(g * 128 + lr2) * 2 + 0]     = sl[mi];
            pb[(g * 128 + lr2) * 2 + 1]     = ql[mi];
            pb[(g * 128 + lr2 + 8) * 2 + 0] = sh_[mi];
            pb[(g * 128 + lr2 + 8) * 2 + 1] = qh_[mi];
        }
    }
    __syncthreads();
    if (tid < 128) {
        float s = 0.f, q = 0.f;
#pragma unroll
        for (int g = 0; g < 4; ++g) {
            s += pb[(g * 128 + tid) * 2 + 0];
            q += pb[(g * 128 + tid) * 2 + 1];
        }
        int pidx = blockIdx.y * gridDim.z + blockIdx.z;
        part[((size_t)pidx * M + mBase + tid) * 2 + 0] = s;
        part[((size_t)pidx * M + mBase + tid) * 2 + 1] = q;
    }
}

// ---------------- BN finalize (warp per channel) ----------------
__global__ void bn_finalize(const float* __restrict__ part,
                            const float* __restrict__ gamma,
                            const float* __restrict__ beta,
                            float* __restrict__ scl, float* __restrict__ shf, int C)
{
    int c = (blockIdx.x * 256 + threadIdx.x) >> 5;
    int lane = threadIdx.x & 31;
    if (c >= C) return;
    float2 a = *(const float2*)&part[((size_t)lane * C + c) * 2];
    float2 b = *(const float2*)&part[((size_t)(lane + 32) * C + c) * 2];
    float s = a.x + b.x, q = a.y + b.y;
#pragma unroll
    for (int off = 16; off > 0; off >>= 1) {
        s += __shfl_xor_sync(0xffffffffu, s, off);
        q += __shfl_xor_sync(0xffffffffu, q, off);
    }
    if (lane == 0) {
        const float invN = 1.f / (NB * NPix);
        float mean = s * invN;
        float var  = q * invN - mean * mean;
        float sc   = gamma[c] * rsqrtf(var + 1e-5f);
        scl[c] = sc;
        shf[c] = beta[c] - mean * sc;
    }
}

// ---------------- flash attention: dv-split (grid z=2), 2 CTAs/SM ---------
#define FL_STG_B 12800
#define FL_QH_OFF (2 * FL_STG_B)
#define FL_SMEM 34304

__global__ void __launch_bounds__(256, 2) flash_attn(const __half* __restrict__ qhg,
                                                     const __half* __restrict__ kh,
                                                     const __half* __restrict__ vh,
                                                     const float* __restrict__ scl,
                                                     const float* __restrict__ shf,
                                                     __half* __restrict__ obuf)
{
    extern __shared__ float fsm[];
    const uint32_t sbase = (uint32_t)__cvta_generic_to_shared(fsm);
    __half* Qh = (__half*)((char*)fsm + FL_QH_OFF);
    float* Os = fsm;

    const int bh = blockIdx.y, b = bh >> 3, h = bh & 7;
    const int qBase = blockIdx.x * 128;
    const int dvh = blockIdx.z * 64;
    const int tid = threadIdx.x, wid = tid >> 5, lane = tid & 31;
    const int gid = lane >> 2, tid4 = lane & 3;
    const int lt = lane >> 3, lr = lane & 7;
    const __half* qhb = qhg + (size_t)(bh * 32) * NPix;
    const __half* khb = kh + (size_t)(bh * 32) * NPix;
    const __half* vbase = vh + (size_t)(bh * 128 + dvh) * NPix;

#define FL_ISSUE(i_) do {                                                      \
        int _k0 = (i_) << 6;                                                   \
        uint32_t sa = sbase + ((i_) & 1) * FL_STG_B;                           \
        {                                                                      \
            int r = tid >> 3, j = tid & 7;                                     \
            cp16(sa + r * 144 + j * 16,                                        \
                 &khb[(size_t)r * NPix + _k0 + (j << 3)]);                     \
        }                                                                      \
        _Pragma("unroll")                                                      \
        for (int t = 0; t < 2; ++t) {                                          \
            int c = tid + t * 256;                                             \
            int dv = c >> 3, j = c & 7;                                        \
            cp16(sa + 4608 + dv * 128 + ((j ^ (dv & 7)) << 4),                 \
                 &vbase[(size_t)dv * NPix + _k0 + (j << 3)]);                  \
        }                                                                      \
    } while (0)

    FL_ISSUE(0); CP_COMMIT;

    for (int i = tid; i < 32 * 128; i += 256) {
        int d = i >> 7, q = i & 127;
        int chq = h * 192 + d, chk = chq + DK;
        float fac = scl[chk] * 0.17677669529663687f * 1.4426950408889634f;
        float qv = __half2float(qhb[(size_t)d * NPix + qBase + q]);
        Qh[d * 136 + q] = __float2half((qv * scl[chq] + shf[chq]) * fac);
    }
    __syncthreads();

    uint32_t qf[2][4];
    {
        uint32_t qaddr = sbase + FL_QH_OFF + ((lt & 1) * 8 + lr) * 272 +
                         (wid * 16 + (lt >> 1) * 8) * 2;
#pragma unroll
        for (int ks = 0; ks < 2; ++ks) {
            uint32_t r[4];
            ldm_x4t(r, qaddr + ks * 16 * 272);
            qf[ks][0] = r[0]; qf[ks][1] = r[2]; qf[ks][2] = r[1]; qf[ks][3] = r[3];
        }
    }

    const uint32_t kldm = ((lt & 1) * 8 + lr) * 144 + (lt >> 1) * 16;

    float o[8][4];
#pragma unroll
    for (int nt = 0; nt < 8; ++nt)
#pragma unroll
        for (int r = 0; r < 4; ++r) o[nt][r] = 0.f;
    float m0 = -1e30f, m1 = -1e30f, l0 = 0.f, l1 = 0.f;

    for (int it = 0; it < 16; ++it) {
        __syncthreads();
        if (it + 1 < 16) { FL_ISSUE(it + 1); CP_COMMIT; CP_WAIT1; }
        else             { CP_WAIT0; }
        __syncthreads();

        uint32_t sK = sbase + (it & 1) * FL_STG_B;
        const char* Vc = (const char*)fsm + (it & 1) * FL_STG_B + 4608;

        float s[8][4];
#pragma unroll
        for (int ni = 0; ni < 8; ++ni)
#pragma unroll
            for (int r = 0; r < 4; ++r) s[ni][r] = 0.f;
#pragma unroll
        for (int ks = 0; ks < 2; ++ks) {
#pragma unroll
            for (int g4 = 0; g4 < 4; ++g4) {
                uint32_t kb[4];
                ldm_x4t(kb, sK + kldm + ks * 2304 + g4 * 32);
                mma_f16_16x8x16(s[g4 * 2],     qf[ks], kb[0], kb[1]);
                mma_f16_16x8x16(s[g4 * 2 + 1], qf[ks], kb[2], kb[3]);
            }
        }

        float t0 = -1e30f, t1 = -1e30f;
#pragma unroll
        for (int ni = 0; ni < 8; ++ni) {
            t0 = fmaxf(t0, fmaxf(s[ni][0], s[ni][1]));
            t1 = fmaxf(t1, fmaxf(s[ni][2], s[ni][3]));
        }
        t0 = fmaxf(t0, __shfl_xor_sync(0xffffffffu, t0, 1));
        t0 = fmaxf(t0, __shfl_xor_sync(0xffffffffu, t0, 2));
        t1 = fmaxf(t1, __shfl_xor_sync(0xffffffffu, t1, 1));
        t1 = fmaxf(t1, __shfl_xor_sync(0xffffffffu, t1, 2));
        float mn0 = fmaxf(m0, t0), mn1 = fmaxf(m1, t1);
        float a0 = ex2f(m0 - mn0), a1 = ex2f(m1 - mn1);
        m0 = mn0; m1 = mn1;

        float ps0 = 0.f, ps1 = 0.f;
#pragma unroll
        for (int ni = 0; ni < 8; ++ni) {
            s[ni][0] = ex2f(s[ni][0] - mn0);
            s[ni][1] = ex2f(s[ni][1] - mn0);
            s[ni][2] = ex2f(s[ni][2] - mn1);
            s[ni][3] = ex2f(s[ni][3] - mn1);
            ps0 += s[ni][0] + s[ni][1];
            ps1 += s[ni][2] + s[ni][3];
        }
        ps0 += __shfl_xor_sync(0xffffffffu, ps0, 1);
        ps0 += __shfl_xor_sync(0xffffffffu, ps0, 2);
        ps1 += __shfl_xor_sync(0xffffffffu, ps1, 1);
        ps1 += __shfl_xor_sync(0xffffffffu, ps1, 2);
        l0 = l0 * a0 + ps0;
        l1 = l1 * a1 + ps1;

#pragma unroll
        for (int nt = 0; nt < 8; ++nt) {
            o[nt][0] *= a0; o[nt][1] *= a0;
            o[nt][2] *= a1; o[nt][3] *= a1;
        }

#pragma unroll
        for (int j = 0; j < 4; ++j) {
            uint32_t af[4];
            asm("cvt.rn.f16x2.f32 %0, %1, %2;" : "=r"(af[0]) : "f"(s[2*j][1]),   "f"(s[2*j][0]));
            asm("cvt.rn.f16x2.f32 %0, %1, %2;" : "=r"(af[1]) : "f"(s[2*j][3]),   "f"(s[2*j][2]));
            asm("cvt.rn.f16x2.f32 %0, %1, %2;" : "=r"(af[2]) : "f"(s[2*j+1][1]), "f"(s[2*j+1][0]));
            asm("cvt.rn.f16x2.f32 %0, %1, %2;" : "=r"(af[3]) : "f"(s[2*j+1][3]), "f"(s[2*j+1][2]));
#pragma unroll
            for (int nt = 0; nt < 8; ++nt) {
                int dv = nt * 8 + gid;
                uint32_t b0 = *(const uint32_t*)(Vc + dv * 128 + (((2*j)     ^ (dv & 7)) << 4) + 4 * tid4);
                uint32_t b1 = *(const uint32_t*)(Vc + dv * 128 + (((2*j + 1) ^ (dv & 7)) << 4) + 4 * tid4);
                mma_f16_16x8x16(o[nt], af, b0, b1);
            }
        }
    }
#undef FL_ISSUE

    float inv0 = 1.f / l0, inv1 = 1.f / l1;
    __syncthreads();
#pragma unroll
    for (int nt = 0; nt < 8; ++nt) {
        int dvl = nt * 8 + 2 * tid4;
        int q   = wid * 16 + gid;
        Os[(size_t)dvl * 132 + q]           = o[nt][0] * inv0;
        Os[(size_t)(dvl + 1) * 132 + q]     = o[nt][1] * inv0;
        Os[(size_t)dvl * 132 + q + 8]       = o[nt][2] * inv1;
        Os[(size_t)(dvl + 1) * 132 + q + 8] = o[nt][3] * inv1;
    }
    __syncthreads();
    for (int i = tid; i < 64 * 32; i += 256) {
        int dvl = i >> 5, q4 = (i & 31) << 2;
        int chv = h * 192 + 2 * DK + dvh + dvl;
        float sc = scl[chv], sh = shf[chv];
        int ch = b * 1024 + h * 128 + dvh + dvl;
        float4 v = *(float4*)&Os[dvl * 132 + q4];
        v.x = gelu_exact(v.x * sc + sh); v.y = gelu_exact(v.y * sc + sh);
        v.z = gelu_exact(v.z * sc + sh); v.w = gelu_exact(v.w * sc + sh);
        __half2* dst = (__half2*)(obuf + (size_t)ch * NPix + qBase + q4);
        dst[0] = __floats2half2_rn(v.x, v.y);
        dst[1] = __floats2half2_rn(v.z, v.w);
    }
}

// ---------------- elementwise ----------------
__global__ void resadd_bn_dual(const float* __restrict__ x, const float* __restrict__ y,
                               const float* __restrict__ scl, const float* __restrict__ shf,
                               float* __restrict__ o, __half* __restrict__ oh,
                               int C, int total4)
{
    int i = blockIdx.x * 256 + threadIdx.x;
    if (i >= total4) return;
    int ch = (i >> 8) % C;
    float sc = scl[ch], sh = shf[ch];
    float4 a = ((const float4*)x)[i];
    float4 c = ((const float4*)y)[i];
    a.x += c.x * sc + sh; a.y += c.y * sc + sh;
    a.z += c.z * sc + sh; a.w += c.w * sc + sh;
    ((float4*)o)[i] = a;
    __half2* d = (__half2*)oh + 2 * i;
    d[0] = __floats2half2_rn(a.x, a.y);
    d[1] = __floats2half2_rn(a.z, a.w);
}
__global__ void resadd_bn(const float* __restrict__ x, const float* __restrict__ y,
                          const float* __restrict__ scl, const float* __restrict__ shf,
                          float* __restrict__ o, int C, int total4)
{
    int i = blockIdx.x * 256 + threadIdx.x;
    if (i >= total4) return;
    int ch = (i >> 8) % C;
    float sc = scl[ch], sh = shf[ch];
    float4 a = ((const float4*)x)[i];
    float4 c = ((const float4*)y)[i];
    a.x += c.x * sc + sh; a.y += c.y * sc + sh;
    a.z += c.z * sc + sh; a.w += c.w * sc + sh;
    ((float4*)o)[i] = a;
}
__global__ void bn_gelu_half(const float* __restrict__ y, __half* __restrict__ oh,
                             const float* __restrict__ scl,
                             const float* __restrict__ shf, int C, int total4)
{
    int i = blockIdx.x * 256 + threadIdx.x;
    if (i >= total4) return;
    int ch = (i >> 8) % C;
    float sc = scl[ch], sh = shf[ch];
    float4 v = ((const float4*)y)[i];
    v.x = gelu_exact(v.x * sc + sh); v.y = gelu_exact(v.y * sc + sh);
    v.z = gelu_exact(v.z * sc + sh); v.w = gelu_exact(v.w * sc + sh);
    __half2* d = (__half2*)oh + 2 * i;
    d[0] = __floats2half2_rn(v.x, v.y);
    d[1] = __floats2half2_rn(v.z, v.w);
}

// ---------------- host ----------------
extern "C" void kernel_launch(void* const* d_in, const int* in_sizes, int n_in,
                              void* d_out, int out_size)
{
    const float* x       = (const float*)d_in[0];
    const float* w_qkv   = (const float*)d_in[1];
    const float* gq      = (const float*)d_in[2];
    const float* bq      = (const float*)d_in[3];
    const float* w_merge = (const float*)d_in[4];
    const float* gm      = (const float*)d_in[5];
    const float* bm      = (const float*)d_in[6];
    const float* w_fc1   = (const float*)d_in[7];
    const float* g1      = (const float*)d_in[8];
    const float* b1      = (const float*)d_in[9];
    const float* w_fc2   = (const float*)d_in[10];
    const float* g2      = (const float*)d_in[11];
    const float* b2      = (const float*)d_in[12];
    float* out = (float*)d_out;

    float *y2, *xr, *h1, *y3, *part;
    __half *qh, *kh, *vh, *obuf, *xh, *xrh, *h1h, *wq, *wm, *w1, *w2;
    float *scq, *shq, *scm, *shm, *sc1, *sh1, *sc2, *sh2;
    cudaGetSymbolAddress((void**)&qh,   g_qh);
    cudaGetSymbolAddress((void**)&kh,   g_kh);
    cudaGetSymbolAddress((void**)&vh,   g_vh);
    cudaGetSymbolAddress((void**)&obuf, g_obuf);
    cudaGetSymbolAddress((void**)&y2,   g_y2);
    cudaGetSymbolAddress((void**)&xr,   g_xr);
    cudaGetSymbolAddress((void**)&xrh,  g_xrh);
    cudaGetSymbolAddress((void**)&xh,   g_xh);
    cudaGetSymbolAddress((void**)&h1,   g_h1);
    cudaGetSymbolAddress((void**)&h1h,  g_h1h);
    cudaGetSymbolAddress((void**)&y3,   g_y3);
    cudaGetSymbolAddress((void**)&part, g_part);
    cudaGetSymbolAddress((void**)&scq, g_sc_qkv);
    cudaGetSymbolAddress((void**)&shq, g_sh_qkv);
    cudaGetSymbolAddress((void**)&scm, g_sc_mg);
    cudaGetSymbolAddress((void**)&shm, g_sh_mg);
    cudaGetSymbolAddress((void**)&sc1, g_sc_f1);
    cudaGetSymbolAddress((void**)&sh1, g_sh_f1);
    cudaGetSymbolAddress((void**)&sc2, g_sc_f2);
    cudaGetSymbolAddress((void**)&sh2, g_sh_f2);
    cudaGetSymbolAddress((void**)&wq, g_wq);
    cudaGetSymbolAddress((void**)&wm, g_wm);
    cudaGetSymbolAddress((void**)&w1, g_w1);
    cudaGetSymbolAddress((void**)&w2, g_w2);

    cudaFuncSetAttribute(f16_gemm, cudaFuncAttributeMaxDynamicSharedMemorySize, GEMM_SMEM);
    cudaFuncSetAttribute(flash_attn, cudaFuncAttributeMaxDynamicSharedMemorySize, FL_SMEM);

    round_all<<<4608, 256>>>(w_qkv, wq, w_merge, wm, w_fc1, w1, w_fc2, w2, x, xh);

    f16_gemm<<<dim3(C_QKV/128, NPix/128, NB), 256, GEMM_SMEM>>>(wq, xh, nullptr, part, qh, kh, vh, C_QKV, NPix, C_IN);
    bn_finalize<<<C_QKV / 8, 256>>>(part, gq, bq, scq, shq, C_QKV);
    flash_attn<<<dim3(8, 64, 2), 256, FL_SMEM>>>(qh, kh, vh, scq, shq, obuf);
    f16_gemm<<<dim3(C_MG/128, NPix/128, NB), 256, GEMM_SMEM>>>(wm, obuf, y2, part, nullptr, nullptr, nullptr, C_MG, NPix, 1024);
    bn_finalize<<<C_MG / 8, 256>>>(part, gm, bm, scm, shm, C_MG);
    resadd_bn_dual<<<(NB * C_IN * NPix / 4 + 255) / 256, 256>>>(x, y2, scm, shm, xr, xrh, C_MG, NB * C_IN * NPix / 4);
    f16_gemm<<<dim3(C_F1/128, NPix/128, NB), 256, GEMM_SMEM>>>(w1, xrh, h1, part, nullptr, nullptr, nullptr, C_F1, NPix, C_IN);
    bn_finalize<<<C_F1 / 8, 256>>>(part, g1, b1, sc1, sh1, C_F1);
    bn_gelu_half<<<(NB * C_F1 * NPix / 4 + 255) / 256, 256>>>(h1, h1h, sc1, sh1, C_F1, NB * C_F1 * NPix / 4);
    f16_gemm<<<dim3(C_F2/128, NPix/128, NB), 256, GEMM_SMEM>>>(w2, h1h, y3, part, nullptr, nullptr, nullptr, C_F2, NPix, C_F1);
    bn_finalize<<<C_F2 / 8, 256>>>(part, g2, b2, sc2, sh2, C_F2);
    resadd_bn<<<(NB * C_F2 * NPix / 4 + 255) / 256, 256>>>(xr, y3, sc2, sh2, out, C_F2, NB * C_F2 * NPix / 4);
}